// round 1
// baseline (speedup 1.0000x reference)
#include <cuda_runtime.h>
#include <math.h>

#define KC 16
#define DD 8
#define NPAIR 8
#define NCOEF 45              // 36 tri-W + 8 (-m) + 1 const
#define TOTC (NPAIR * NCOEF)  // 360

// packed f32x2 coefficient table: for pair p (components 2p, 2p+1)
//   idx 0..35   : Linv[i][j] for i=0..7, j<=i  (t = i*(i+1)/2 + j)
//   idx 36+i    : -(Linv @ mu)[i]
//   idx 44      : log_softmax(pi) - half_logdet - 4*log(2*pi)
__device__ unsigned long long g_coef[TOTC];

__device__ __forceinline__ unsigned long long pack2(float lo, float hi) {
    unsigned long long r;
    asm("mov.b64 %0, {%1, %2};" : "=l"(r) : "f"(lo), "f"(hi));
    return r;
}
__device__ __forceinline__ void unpack2(unsigned long long v, float& lo, float& hi) {
    asm("mov.b64 {%0, %1}, %2;" : "=f"(lo), "=f"(hi) : "l"(v));
}
#define FMA2(d, a, b, c) \
    asm("fma.rn.f32x2 %0, %1, %2, %3;" : "=l"(d) : "l"(a), "l"(b), "l"(c))

// ---------------------------------------------------------------------------
// Precompute: per component k, cov = tril(C) tril(C)^T + eps I, Cholesky L,
// Linv = L^-1, fold means and mixture/normalization constants.
// ---------------------------------------------------------------------------
__global__ void gmm_precompute(const float* __restrict__ means,
                               const float* __restrict__ chol,
                               const float* __restrict__ pi) {
    int k = threadIdx.x;
    if (k >= KC) return;

    float L0[DD][DD];
    #pragma unroll
    for (int i = 0; i < DD; ++i)
        #pragma unroll
        for (int j = 0; j < DD; ++j)
            L0[i][j] = (j <= i) ? chol[k * 64 + i * 8 + j] : 0.0f;

    // cov = L0 @ L0^T + eps I
    float A[DD][DD];
    for (int i = 0; i < DD; ++i) {
        for (int l = 0; l < DD; ++l) {
            float s = 0.0f;
            for (int j = 0; j < DD; ++j) s += L0[i][j] * L0[l][j];
            A[i][l] = s;
        }
        A[i][i] += 1e-6f;
    }

    // Cholesky
    float L[DD][DD];
    for (int c = 0; c < DD; ++c) {
        float s = A[c][c];
        for (int l = 0; l < c; ++l) s -= L[c][l] * L[c][l];
        L[c][c] = sqrtf(s);
        for (int r = c + 1; r < DD; ++r) {
            float t = A[r][c];
            for (int l = 0; l < c; ++l) t -= L[r][l] * L[c][l];
            L[r][c] = t / L[c][c];
        }
    }

    float hld = 0.0f;
    for (int i = 0; i < DD; ++i) hld += logf(L[i][i]);

    // lower-triangular inverse
    float Li[DD][DD];
    for (int i = 0; i < DD; ++i)
        for (int j = 0; j < DD; ++j) Li[i][j] = 0.0f;
    for (int i = 0; i < DD; ++i) Li[i][i] = 1.0f / L[i][i];
    for (int i = 0; i < DD; ++i)
        for (int j = 0; j < i; ++j) {
            float s = 0.0f;
            for (int l = j; l < i; ++l) s += L[i][l] * Li[l][j];
            Li[i][j] = -s / L[i][i];
        }

    // m = Linv @ mu
    float m[DD];
    for (int i = 0; i < DD; ++i) {
        float s = 0.0f;
        for (int j = 0; j <= i; ++j) s += Li[i][j] * means[k * 8 + j];
        m[i] = s;
    }

    // log_softmax(pi)[k]
    float pmax = pi[0];
    for (int t = 1; t < KC; ++t) pmax = fmaxf(pmax, pi[t]);
    float se = 0.0f;
    for (int t = 0; t < KC; ++t) se += expf(pi[t] - pmax);
    float lsm = pi[k] - (pmax + logf(se));

    const float LOG2PI = 1.8378770664093453f;
    float ck = lsm - hld - 4.0f * LOG2PI;

    // write my lane of the packed pair table (32-bit half-writes)
    int p = k >> 1, lane = k & 1;
    float* gf = reinterpret_cast<float*>(g_coef);
    int base = p * NCOEF;
    int t = 0;
    for (int i = 0; i < DD; ++i)
        for (int j = 0; j <= i; ++j, ++t)
            gf[2 * (base + t) + lane] = Li[i][j];
    for (int i = 0; i < DD; ++i)
        gf[2 * (base + 36 + i) + lane] = -m[i];
    gf[2 * (base + 44) + lane] = ck;
}

// ---------------------------------------------------------------------------
// Main kernel: 2 points per thread, components packed in f32x2 pairs.
// ---------------------------------------------------------------------------
__device__ __forceinline__ float lse16(const unsigned long long* lp) {
    float v[KC];
    #pragma unroll
    for (int p = 0; p < NPAIR; ++p) unpack2(lp[p], v[2 * p], v[2 * p + 1]);
    float m = v[0];
    #pragma unroll
    for (int k = 1; k < KC; ++k) m = fmaxf(m, v[k]);
    float s = 0.0f;
    #pragma unroll
    for (int k = 0; k < KC; ++k) s += __expf(v[k] - m);
    return m + __logf(s);
}

__global__ void __launch_bounds__(256) gmm_kernel(const float* __restrict__ x,
                                                  float* __restrict__ out,
                                                  int n) {
    __shared__ unsigned long long sc[TOTC];
    for (int i = threadIdx.x; i < TOTC; i += blockDim.x) sc[i] = g_coef[i];
    __syncthreads();

    int t = blockIdx.x * blockDim.x + threadIdx.x;
    int i0 = t * 2;
    if (i0 >= n) return;

    const float4* xv = reinterpret_cast<const float4*>(x + (size_t)i0 * DD);
    float4 a0 = xv[0];
    float4 a1 = xv[1];
    float4 b0 = xv[2];
    float4 b1 = xv[3];

    unsigned long long X0[DD], X1[DD];
    X0[0] = pack2(a0.x, a0.x); X0[1] = pack2(a0.y, a0.y);
    X0[2] = pack2(a0.z, a0.z); X0[3] = pack2(a0.w, a0.w);
    X0[4] = pack2(a1.x, a1.x); X0[5] = pack2(a1.y, a1.y);
    X0[6] = pack2(a1.z, a1.z); X0[7] = pack2(a1.w, a1.w);
    X1[0] = pack2(b0.x, b0.x); X1[1] = pack2(b0.y, b0.y);
    X1[2] = pack2(b0.z, b0.z); X1[3] = pack2(b0.w, b0.w);
    X1[4] = pack2(b1.x, b1.x); X1[5] = pack2(b1.y, b1.y);
    X1[6] = pack2(b1.z, b1.z); X1[7] = pack2(b1.w, b1.w);

    const unsigned long long NEGH = pack2(-0.5f, -0.5f);
    unsigned long long lp0[NPAIR], lp1[NPAIR];

    #pragma unroll
    for (int p = 0; p < NPAIR; ++p) {
        const unsigned long long* cp = &sc[p * NCOEF];
        unsigned long long q0 = 0ull, q1 = 0ull;
        int tt = 0;
        #pragma unroll
        for (int i = 0; i < DD; ++i) {
            unsigned long long y0 = cp[36 + i];
            unsigned long long y1 = y0;
            #pragma unroll
            for (int j = 0; j <= i; ++j, ++tt) {
                unsigned long long w = cp[tt];
                FMA2(y0, w, X0[j], y0);
                FMA2(y1, w, X1[j], y1);
            }
            FMA2(q0, y0, y0, q0);
            FMA2(q1, y1, y1, q1);
        }
        unsigned long long c2 = cp[44];
        FMA2(lp0[p], q0, NEGH, c2);
        FMA2(lp1[p], q1, NEGH, c2);
    }

    out[i0]     = lse16(lp0);
    out[i0 + 1] = lse16(lp1);
}

// ---------------------------------------------------------------------------
extern "C" void kernel_launch(void* const* d_in, const int* in_sizes, int n_in,
                              void* d_out, int out_size) {
    const float* x     = (const float*)d_in[0];
    const float* means = (const float*)d_in[1];
    const float* chol  = (const float*)d_in[2];
    const float* pi    = (const float*)d_in[3];
    float* out = (float*)d_out;

    int n = in_sizes[0] / DD;  // number of points

    gmm_precompute<<<1, 32>>>(means, chol, pi);

    int threads = 256;
    int pts_per_block = threads * 2;
    int blocks = (n + pts_per_block - 1) / pts_per_block;
    gmm_kernel<<<blocks, threads>>>(x, out, n);
}

// round 2
// speedup vs baseline: 1.1000x; 1.1000x over previous
#include <cuda_runtime.h>
#include <math.h>

#define KC 16
#define DD 8
#define NPAIR 8
#define NCOEF 45              // 36 tri-W + 8 (-m) + 1 shifted const
#define TOTC (NPAIR * NCOEF)  // 360

// packed f32x2 coefficient table: for pair p (components 2p, 2p+1)
//   idx 0..35   : Linv[i][j] for i=0..7, j<=i  (t = i*(i+1)/2 + j)
//   idx 36+i    : -(Linv @ mu)[i]
//   idx 44      : (log_softmax(pi) - half_logdet - 4*log(2*pi)) - cmax
__device__ unsigned long long g_coef[TOTC];
__device__ float g_cmax;

__device__ __forceinline__ unsigned long long pack2(float lo, float hi) {
    unsigned long long r;
    asm("mov.b64 %0, {%1, %2};" : "=l"(r) : "f"(lo), "f"(hi));
    return r;
}
__device__ __forceinline__ void unpack2(unsigned long long v, float& lo, float& hi) {
    asm("mov.b64 {%0, %1}, %2;" : "=f"(lo), "=f"(hi) : "l"(v));
}
#define FMA2(d, a, b, c) \
    asm("fma.rn.f32x2 %0, %1, %2, %3;" : "=l"(d) : "l"(a), "l"(b), "l"(c))

// ---------------------------------------------------------------------------
// Precompute (1 warp of 16 threads): per component k,
// cov = tril(C) tril(C)^T + eps I, Cholesky L, Linv = L^-1,
// fold means, mixture weight, normalization, and the global shift cmax.
// ---------------------------------------------------------------------------
__global__ void gmm_precompute(const float* __restrict__ means,
                               const float* __restrict__ chol,
                               const float* __restrict__ pi) {
    int k = threadIdx.x;

    float L0[DD][DD];
    #pragma unroll
    for (int i = 0; i < DD; ++i)
        #pragma unroll
        for (int j = 0; j < DD; ++j)
            L0[i][j] = (j <= i) ? chol[k * 64 + i * 8 + j] : 0.0f;

    // cov = L0 @ L0^T + eps I
    float A[DD][DD];
    for (int i = 0; i < DD; ++i) {
        for (int l = 0; l < DD; ++l) {
            float s = 0.0f;
            for (int j = 0; j < DD; ++j) s += L0[i][j] * L0[l][j];
            A[i][l] = s;
        }
        A[i][i] += 1e-6f;
    }

    // Cholesky
    float L[DD][DD];
    for (int c = 0; c < DD; ++c) {
        float s = A[c][c];
        for (int l = 0; l < c; ++l) s -= L[c][l] * L[c][l];
        L[c][c] = sqrtf(s);
        float inv = __fdividef(1.0f, L[c][c]);
        for (int r = c + 1; r < DD; ++r) {
            float t = A[r][c];
            for (int l = 0; l < c; ++l) t -= L[r][l] * L[c][l];
            L[r][c] = t * inv;
        }
    }

    float hld = 0.0f;
    for (int i = 0; i < DD; ++i) hld += logf(L[i][i]);

    // lower-triangular inverse
    float Li[DD][DD];
    for (int i = 0; i < DD; ++i)
        for (int j = 0; j < DD; ++j) Li[i][j] = 0.0f;
    for (int i = 0; i < DD; ++i) Li[i][i] = __fdividef(1.0f, L[i][i]);
    for (int i = 0; i < DD; ++i)
        for (int j = 0; j < i; ++j) {
            float s = 0.0f;
            for (int l = j; l < i; ++l) s += L[i][l] * Li[l][j];
            Li[i][j] = -s * Li[i][i];
        }

    // m = Linv @ mu
    float m[DD];
    for (int i = 0; i < DD; ++i) {
        float s = 0.0f;
        for (int j = 0; j <= i; ++j) s += Li[i][j] * means[k * 8 + j];
        m[i] = s;
    }

    // log_softmax(pi)[k]
    float pmax = pi[0];
    for (int t = 1; t < KC; ++t) pmax = fmaxf(pmax, pi[t]);
    float se = 0.0f;
    for (int t = 0; t < KC; ++t) se += expf(pi[t] - pmax);
    float lsm = pi[k] - (pmax + logf(se));

    const float LOG2PI = 1.8378770664093453f;
    float ck = lsm - hld - 4.0f * LOG2PI;

    // shuffle-max over the 16 lanes -> global shift
    float cm = ck;
    #pragma unroll
    for (int off = 8; off; off >>= 1)
        cm = fmaxf(cm, __shfl_xor_sync(0xFFFFu, cm, off, 16));
    if (k == 0) g_cmax = cm;
    ck -= cm;

    // write my lane of the packed pair table (32-bit half-writes)
    int p = k >> 1, lane = k & 1;
    float* gf = reinterpret_cast<float*>(g_coef);
    int base = p * NCOEF;
    int t = 0;
    for (int i = 0; i < DD; ++i)
        for (int j = 0; j <= i; ++j, ++t)
            gf[2 * (base + t) + lane] = Li[i][j];
    for (int i = 0; i < DD; ++i)
        gf[2 * (base + 36 + i) + lane] = -m[i];
    gf[2 * (base + 44) + lane] = ck;
}

// ---------------------------------------------------------------------------
// Main kernel: 2 points/thread, components in f32x2 pairs, online exp-sum
// against the fixed uniform shift (no lp[] storage, no two-pass LSE).
// ---------------------------------------------------------------------------
__global__ void __launch_bounds__(256) gmm_kernel(const float* __restrict__ x,
                                                  float* __restrict__ out,
                                                  int n) {
    __shared__ unsigned long long sc[TOTC];
    #pragma unroll 2
    for (int i = threadIdx.x; i < TOTC; i += 256) sc[i] = g_coef[i];
    __syncthreads();

    int t = blockIdx.x * 256 + threadIdx.x;
    int i0 = t * 2;
    if (i0 >= n) return;

    const float4* xv = reinterpret_cast<const float4*>(x + (size_t)i0 * DD);
    float4 a0 = xv[0];
    float4 a1 = xv[1];
    float4 b0 = xv[2];
    float4 b1 = xv[3];

    unsigned long long X0[DD], X1[DD];
    X0[0] = pack2(a0.x, a0.x); X0[1] = pack2(a0.y, a0.y);
    X0[2] = pack2(a0.z, a0.z); X0[3] = pack2(a0.w, a0.w);
    X0[4] = pack2(a1.x, a1.x); X0[5] = pack2(a1.y, a1.y);
    X0[6] = pack2(a1.z, a1.z); X0[7] = pack2(a1.w, a1.w);
    X1[0] = pack2(b0.x, b0.x); X1[1] = pack2(b0.y, b0.y);
    X1[2] = pack2(b0.z, b0.z); X1[3] = pack2(b0.w, b0.w);
    X1[4] = pack2(b1.x, b1.x); X1[5] = pack2(b1.y, b1.y);
    X1[6] = pack2(b1.z, b1.z); X1[7] = pack2(b1.w, b1.w);

    const unsigned long long NEGH = pack2(-0.5f, -0.5f);
    float s0a = 0.0f, s0b = 0.0f, s1a = 0.0f, s1b = 0.0f;

    #pragma unroll
    for (int p = 0; p < NPAIR; ++p) {
        const unsigned long long* cp = &sc[p * NCOEF];
        unsigned long long q0 = 0ull, q1 = 0ull;
        int tt = 0;
        #pragma unroll
        for (int i = 0; i < DD; ++i) {
            unsigned long long y0 = cp[36 + i];
            unsigned long long y1 = y0;
            #pragma unroll
            for (int j = 0; j <= i; ++j, ++tt) {
                unsigned long long w = cp[tt];
                FMA2(y0, w, X0[j], y0);
                FMA2(y1, w, X1[j], y1);
            }
            FMA2(q0, y0, y0, q0);
            FMA2(q1, y1, y1, q1);
        }
        unsigned long long c2 = cp[44], l0, l1;
        FMA2(l0, q0, NEGH, c2);
        FMA2(l1, q1, NEGH, c2);
        float va, vb;
        unpack2(l0, va, vb);
        s0a += __expf(va); s0b += __expf(vb);
        unpack2(l1, va, vb);
        s1a += __expf(va); s1b += __expf(vb);
    }

    float cm = g_cmax;
    float2 r;
    r.x = cm + __logf(s0a + s0b);
    r.y = cm + __logf(s1a + s1b);
    *reinterpret_cast<float2*>(out + i0) = r;
}

// ---------------------------------------------------------------------------
extern "C" void kernel_launch(void* const* d_in, const int* in_sizes, int n_in,
                              void* d_out, int out_size) {
    const float* x     = (const float*)d_in[0];
    const float* means = (const float*)d_in[1];
    const float* chol  = (const float*)d_in[2];
    const float* pi    = (const float*)d_in[3];
    float* out = (float*)d_out;

    int n = in_sizes[0] / DD;  // number of points

    gmm_precompute<<<1, 16>>>(means, chol, pi);

    int threads = 256;
    int pts_per_block = threads * 2;
    int blocks = (n + pts_per_block - 1) / pts_per_block;
    gmm_kernel<<<blocks, threads>>>(x, out, n);
}

// round 3
// speedup vs baseline: 1.2153x; 1.1048x over previous
#include <cuda_runtime.h>
#include <math.h>

#define KC 16
#define DD 8
#define NPAIR 8
#define NCOEF 46              // 36 tri-W + 8 (-m) + 1 shifted const + 1 pad (16B-align)
#define TOTC (NPAIR * NCOEF)  // 368

// packed f32x2 coefficient table: for pair p (components 2p, 2p+1)
//   idx 0..35   : Linv[i][j] for i=0..7, j<=i  (t = i*(i+1)/2 + j)
//   idx 36+i    : -(Linv @ mu)[i]
//   idx 44      : (log_softmax(pi) - half_logdet - 4*log(2*pi) - cmax) * log2(e)
//   idx 45      : pad
__device__ __align__(16) unsigned long long g_coef[TOTC];
__device__ float g_cmax;

__device__ __forceinline__ unsigned long long pack2(float lo, float hi) {
    unsigned long long r;
    asm("mov.b64 %0, {%1, %2};" : "=l"(r) : "f"(lo), "f"(hi));
    return r;
}
__device__ __forceinline__ void unpack2(unsigned long long v, float& lo, float& hi) {
    asm("mov.b64 {%0, %1}, %2;" : "=f"(lo), "=f"(hi) : "l"(v));
}
#define FMA2(d, a, b, c) \
    asm("fma.rn.f32x2 %0, %1, %2, %3;" : "=l"(d) : "l"(a), "l"(b), "l"(c))

__device__ __forceinline__ float ex2f(float v) {
    float r;
    asm("ex2.approx.ftz.f32 %0, %1;" : "=f"(r) : "f"(v));
    return r;
}
__device__ __forceinline__ float lg2f(float v) {
    float r;
    asm("lg2.approx.ftz.f32 %0, %1;" : "=f"(r) : "f"(v));
    return r;
}

// triangular index maps: t -> (i, j)
__device__ constexpr int TI[36] = {0, 1,1, 2,2,2, 3,3,3,3, 4,4,4,4,4,
                                   5,5,5,5,5,5, 6,6,6,6,6,6,6, 7,7,7,7,7,7,7,7};
__device__ constexpr int TJ[36] = {0, 0,1, 0,1,2, 0,1,2,3, 0,1,2,3,4,
                                   0,1,2,3,4,5, 0,1,2,3,4,5,6, 0,1,2,3,4,5,6,7};

// ---------------------------------------------------------------------------
// Precompute (16 threads): per component k, cov = tril(C) tril(C)^T + eps I,
// Cholesky L, Linv = L^-1, fold means, weights, normalization, global shift.
// ---------------------------------------------------------------------------
__global__ void gmm_precompute(const float* __restrict__ means,
                               const float* __restrict__ chol,
                               const float* __restrict__ pi) {
    int k = threadIdx.x;

    float L0[DD][DD];
    #pragma unroll
    for (int i = 0; i < DD; ++i)
        #pragma unroll
        for (int j = 0; j < DD; ++j)
            L0[i][j] = (j <= i) ? chol[k * 64 + i * 8 + j] : 0.0f;

    float A[DD][DD];
    for (int i = 0; i < DD; ++i) {
        for (int l = 0; l < DD; ++l) {
            float s = 0.0f;
            for (int j = 0; j < DD; ++j) s += L0[i][j] * L0[l][j];
            A[i][l] = s;
        }
        A[i][i] += 1e-6f;
    }

    float L[DD][DD];
    for (int c = 0; c < DD; ++c) {
        float s = A[c][c];
        for (int l = 0; l < c; ++l) s -= L[c][l] * L[c][l];
        L[c][c] = sqrtf(s);
        float inv = __fdividef(1.0f, L[c][c]);
        for (int r = c + 1; r < DD; ++r) {
            float t = A[r][c];
            for (int l = 0; l < c; ++l) t -= L[r][l] * L[c][l];
            L[r][c] = t * inv;
        }
    }

    float hld = 0.0f;
    for (int i = 0; i < DD; ++i) hld += __logf(L[i][i]);

    float Li[DD][DD];
    for (int i = 0; i < DD; ++i)
        for (int j = 0; j < DD; ++j) Li[i][j] = 0.0f;
    for (int i = 0; i < DD; ++i) Li[i][i] = __fdividef(1.0f, L[i][i]);
    for (int i = 0; i < DD; ++i)
        for (int j = 0; j < i; ++j) {
            float s = 0.0f;
            for (int l = j; l < i; ++l) s += L[i][l] * Li[l][j];
            Li[i][j] = -s * Li[i][i];
        }

    float m[DD];
    for (int i = 0; i < DD; ++i) {
        float s = 0.0f;
        for (int j = 0; j <= i; ++j) s += Li[i][j] * means[k * 8 + j];
        m[i] = s;
    }

    float pmax = pi[0];
    for (int t = 1; t < KC; ++t) pmax = fmaxf(pmax, pi[t]);
    float se = 0.0f;
    for (int t = 0; t < KC; ++t) se += __expf(pi[t] - pmax);
    float lsm = pi[k] - (pmax + __logf(se));

    const float LOG2PI = 1.8378770664093453f;
    const float LOG2E  = 1.4426950408889634f;
    float ck = lsm - hld - 4.0f * LOG2PI;

    float cm = ck;
    #pragma unroll
    for (int off = 8; off; off >>= 1)
        cm = fmaxf(cm, __shfl_xor_sync(0xFFFFu, cm, off, 16));
    if (k == 0) g_cmax = cm;
    float ckp = (ck - cm) * LOG2E;

    int p = k >> 1, lane = k & 1;
    float* gf = reinterpret_cast<float*>(g_coef);
    int base = p * NCOEF;
    int t = 0;
    for (int i = 0; i < DD; ++i)
        for (int j = 0; j <= i; ++j, ++t)
            gf[2 * (base + t) + lane] = Li[i][j];
    for (int i = 0; i < DD; ++i)
        gf[2 * (base + 36 + i) + lane] = -m[i];
    gf[2 * (base + 44) + lane] = ckp;
    gf[2 * (base + 45) + lane] = 0.0f;
}

// ---------------------------------------------------------------------------
// Main kernel: 2 points/thread, components in f32x2 pairs, LDS.128
// coefficient loads, exp2-domain online accumulation with uniform shift.
// ---------------------------------------------------------------------------
__global__ void __launch_bounds__(128) gmm_kernel(const float* __restrict__ x,
                                                  float* __restrict__ out,
                                                  int n) {
    __shared__ __align__(16) unsigned long long sc[TOTC];
    #pragma unroll
    for (int i = threadIdx.x; i < TOTC; i += 128) sc[i] = g_coef[i];
    float cm = g_cmax;
    __syncthreads();

    int t = blockIdx.x * 128 + threadIdx.x;
    int i0 = t * 2;
    if (i0 >= n) return;

    const float4* xv = reinterpret_cast<const float4*>(x + (size_t)i0 * DD);
    float4 a0 = xv[0];
    float4 a1 = xv[1];
    float4 b0 = xv[2];
    float4 b1 = xv[3];

    unsigned long long X0[DD], X1[DD];
    X0[0] = pack2(a0.x, a0.x); X0[1] = pack2(a0.y, a0.y);
    X0[2] = pack2(a0.z, a0.z); X0[3] = pack2(a0.w, a0.w);
    X0[4] = pack2(a1.x, a1.x); X0[5] = pack2(a1.y, a1.y);
    X0[6] = pack2(a1.z, a1.z); X0[7] = pack2(a1.w, a1.w);
    X1[0] = pack2(b0.x, b0.x); X1[1] = pack2(b0.y, b0.y);
    X1[2] = pack2(b0.z, b0.z); X1[3] = pack2(b0.w, b0.w);
    X1[4] = pack2(b1.x, b1.x); X1[5] = pack2(b1.y, b1.y);
    X1[6] = pack2(b1.z, b1.z); X1[7] = pack2(b1.w, b1.w);

    // -0.5 * log2(e): quad -> exp2 domain
    const unsigned long long NEGH = pack2(-0.72134752044448170f, -0.72134752044448170f);
    float s0a = 0.0f, s0b = 0.0f, s1a = 0.0f, s1b = 0.0f;

    #pragma unroll
    for (int p = 0; p < NPAIR; ++p) {
        const ulonglong2* cv = reinterpret_cast<const ulonglong2*>(sc + p * NCOEF);

        ulonglong2 mv0 = cv[18], mv1 = cv[19], mv2 = cv[20], mv3 = cv[21];
        unsigned long long mi[DD];
        mi[0] = mv0.x; mi[1] = mv0.y; mi[2] = mv1.x; mi[3] = mv1.y;
        mi[4] = mv2.x; mi[5] = mv2.y; mi[6] = mv3.x; mi[7] = mv3.y;
        ulonglong2 cc = cv[22];

        unsigned long long q0 = 0ull, q1 = 0ull, y0, y1;

        #pragma unroll
        for (int u = 0; u < 18; ++u) {
            ulonglong2 w = cv[u];
            {
                const int i = TI[2 * u], j = TJ[2 * u];
                if (j == 0) { y0 = mi[i]; y1 = mi[i]; }
                FMA2(y0, w.x, X0[j], y0);
                FMA2(y1, w.x, X1[j], y1);
                if (j == i) { FMA2(q0, y0, y0, q0); FMA2(q1, y1, y1, q1); }
            }
            {
                const int i = TI[2 * u + 1], j = TJ[2 * u + 1];
                if (j == 0) { y0 = mi[i]; y1 = mi[i]; }
                FMA2(y0, w.y, X0[j], y0);
                FMA2(y1, w.y, X1[j], y1);
                if (j == i) { FMA2(q0, y0, y0, q0); FMA2(q1, y1, y1, q1); }
            }
        }

        unsigned long long l0, l1;
        FMA2(l0, q0, NEGH, cc.x);
        FMA2(l1, q1, NEGH, cc.x);
        float va, vb;
        unpack2(l0, va, vb);
        s0a += ex2f(va); s0b += ex2f(vb);
        unpack2(l1, va, vb);
        s1a += ex2f(va); s1b += ex2f(vb);
    }

    const float LN2 = 0.69314718055994531f;
    float2 r;
    r.x = fmaf(LN2, lg2f(s0a + s0b), cm);
    r.y = fmaf(LN2, lg2f(s1a + s1b), cm);
    *reinterpret_cast<float2*>(out + i0) = r;
}

// ---------------------------------------------------------------------------
extern "C" void kernel_launch(void* const* d_in, const int* in_sizes, int n_in,
                              void* d_out, int out_size) {
    const float* x     = (const float*)d_in[0];
    const float* means = (const float*)d_in[1];
    const float* chol  = (const float*)d_in[2];
    const float* pi    = (const float*)d_in[3];
    float* out = (float*)d_out;

    int n = in_sizes[0] / DD;  // number of points

    gmm_precompute<<<1, 16>>>(means, chol, pi);

    int threads = 128;
    int pts_per_block = threads * 2;
    int blocks = (n + pts_per_block - 1) / pts_per_block;
    gmm_kernel<<<blocks, threads>>>(x, out, n);
}

// round 4
// speedup vs baseline: 1.2732x; 1.0477x over previous
#include <cuda_runtime.h>
#include <math.h>

#define KC 16
#define DD 8
#define NPAIR 8
#define NCOEF 46              // 36 tri-W + 8 (-m) + 1 shifted const + 1 pad (16B-align)
#define TOTC (NPAIR * NCOEF)  // 368

// packed f32x2 coefficient table: for pair p (components 2p, 2p+1)
//   idx 0..35   : Linv[i][j] for i=0..7, j<=i  (t = i*(i+1)/2 + j)
//   idx 36+i    : -(Linv @ mu)[i]
//   idx 44      : (log_softmax(pi) - half_logdet - 4*log(2*pi) - cmax) * log2(e)
//   idx 45      : pad
__device__ __align__(16) unsigned long long g_coef[TOTC];
__device__ float g_cmax;

__device__ __forceinline__ unsigned long long pack2(float lo, float hi) {
    unsigned long long r;
    asm("mov.b64 %0, {%1, %2};" : "=l"(r) : "f"(lo), "f"(hi));
    return r;
}
__device__ __forceinline__ void unpack2(unsigned long long v, float& lo, float& hi) {
    asm("mov.b64 {%0, %1}, %2;" : "=f"(lo), "=f"(hi) : "l"(v));
}
#define FMA2(d, a, b, c) \
    asm("fma.rn.f32x2 %0, %1, %2, %3;" : "=l"(d) : "l"(a), "l"(b), "l"(c))

__device__ __forceinline__ float ex2f(float v) {
    float r;
    asm("ex2.approx.ftz.f32 %0, %1;" : "=f"(r) : "f"(v));
    return r;
}
__device__ __forceinline__ float lg2f(float v) {
    float r;
    asm("lg2.approx.ftz.f32 %0, %1;" : "=f"(r) : "f"(v));
    return r;
}

// triangular index maps: t -> (i, j)
__device__ constexpr int TI[36] = {0, 1,1, 2,2,2, 3,3,3,3, 4,4,4,4,4,
                                   5,5,5,5,5,5, 6,6,6,6,6,6,6, 7,7,7,7,7,7,7,7};
__device__ constexpr int TJ[36] = {0, 0,1, 0,1,2, 0,1,2,3, 0,1,2,3,4,
                                   0,1,2,3,4,5, 0,1,2,3,4,5,6, 0,1,2,3,4,5,6,7};

// ---------------------------------------------------------------------------
// Precompute (16 threads): per component k, cov = tril(C) tril(C)^T + eps I,
// Cholesky L, Linv = L^-1, fold means, weights, normalization, global shift.
// ---------------------------------------------------------------------------
__global__ void gmm_precompute(const float* __restrict__ means,
                               const float* __restrict__ chol,
                               const float* __restrict__ pi) {
    int k = threadIdx.x;

    float L0[DD][DD];
    #pragma unroll
    for (int i = 0; i < DD; ++i)
        #pragma unroll
        for (int j = 0; j < DD; ++j)
            L0[i][j] = (j <= i) ? chol[k * 64 + i * 8 + j] : 0.0f;

    float A[DD][DD];
    for (int i = 0; i < DD; ++i) {
        for (int l = 0; l < DD; ++l) {
            float s = 0.0f;
            for (int j = 0; j < DD; ++j) s += L0[i][j] * L0[l][j];
            A[i][l] = s;
        }
        A[i][i] += 1e-6f;
    }

    float L[DD][DD];
    for (int c = 0; c < DD; ++c) {
        float s = A[c][c];
        for (int l = 0; l < c; ++l) s -= L[c][l] * L[c][l];
        L[c][c] = sqrtf(s);
        float inv = __fdividef(1.0f, L[c][c]);
        for (int r = c + 1; r < DD; ++r) {
            float t = A[r][c];
            for (int l = 0; l < c; ++l) t -= L[r][l] * L[c][l];
            L[r][c] = t * inv;
        }
    }

    float hld = 0.0f;
    for (int i = 0; i < DD; ++i) hld += __logf(L[i][i]);

    float Li[DD][DD];
    for (int i = 0; i < DD; ++i)
        for (int j = 0; j < DD; ++j) Li[i][j] = 0.0f;
    for (int i = 0; i < DD; ++i) Li[i][i] = __fdividef(1.0f, L[i][i]);
    for (int i = 0; i < DD; ++i)
        for (int j = 0; j < i; ++j) {
            float s = 0.0f;
            for (int l = j; l < i; ++l) s += L[i][l] * Li[l][j];
            Li[i][j] = -s * Li[i][i];
        }

    float m[DD];
    for (int i = 0; i < DD; ++i) {
        float s = 0.0f;
        for (int j = 0; j <= i; ++j) s += Li[i][j] * means[k * 8 + j];
        m[i] = s;
    }

    float pmax = pi[0];
    for (int t = 1; t < KC; ++t) pmax = fmaxf(pmax, pi[t]);
    float se = 0.0f;
    for (int t = 0; t < KC; ++t) se += __expf(pi[t] - pmax);
    float lsm = pi[k] - (pmax + __logf(se));

    const float LOG2PI = 1.8378770664093453f;
    const float LOG2E  = 1.4426950408889634f;
    float ck = lsm - hld - 4.0f * LOG2PI;

    float cm = ck;
    #pragma unroll
    for (int off = 8; off; off >>= 1)
        cm = fmaxf(cm, __shfl_xor_sync(0xFFFFu, cm, off, 16));
    if (k == 0) g_cmax = cm;
    float ckp = (ck - cm) * LOG2E;

    int p = k >> 1, lane = k & 1;
    float* gf = reinterpret_cast<float*>(g_coef);
    int base = p * NCOEF;
    int t = 0;
    for (int i = 0; i < DD; ++i)
        for (int j = 0; j <= i; ++j, ++t)
            gf[2 * (base + t) + lane] = Li[i][j];
    for (int i = 0; i < DD; ++i)
        gf[2 * (base + 36 + i) + lane] = -m[i];
    gf[2 * (base + 44) + lane] = ckp;
    gf[2 * (base + 45) + lane] = 0.0f;
}

// ---------------------------------------------------------------------------
// Main kernel: 4 points/thread (strided by lane so loads/stores coalesce),
// components in f32x2 pairs, coefficients amortized over 4 points to halve
// smem-crossbar cycles per point. exp2-domain online accumulation.
// ---------------------------------------------------------------------------
__global__ void __launch_bounds__(128, 4) gmm_kernel(const float* __restrict__ x,
                                                     float* __restrict__ out,
                                                     int n) {
    __shared__ __align__(16) unsigned long long sc[TOTC];
    #pragma unroll
    for (int i = threadIdx.x; i < TOTC; i += 128) sc[i] = g_coef[i];
    float cm = g_cmax;
    __syncthreads();

    int warp = threadIdx.x >> 5;
    int lane = threadIdx.x & 31;
    int base = blockIdx.x * 512 + warp * 128 + lane;  // point for k=0; +32 per k

    // load 4 points (lane-strided: 32B lane stride -> 8 lines/wavefront)
    unsigned long long X[4][DD];
    #pragma unroll
    for (int k = 0; k < 4; ++k) {
        int pt = base + 32 * k;
        int idx = pt < n ? pt : n - 1;  // clamp (n is a multiple of 512 in practice)
        const float4* xv = reinterpret_cast<const float4*>(x) + (size_t)idx * 2;
        float4 a = xv[0];
        float4 b = xv[1];
        X[k][0] = pack2(a.x, a.x); X[k][1] = pack2(a.y, a.y);
        X[k][2] = pack2(a.z, a.z); X[k][3] = pack2(a.w, a.w);
        X[k][4] = pack2(b.x, b.x); X[k][5] = pack2(b.y, b.y);
        X[k][6] = pack2(b.z, b.z); X[k][7] = pack2(b.w, b.w);
    }

    // -0.5 * log2(e): quad -> exp2 domain
    const unsigned long long NEGH = pack2(-0.72134752044448170f, -0.72134752044448170f);
    float sa[4] = {0.f, 0.f, 0.f, 0.f};
    float sb[4] = {0.f, 0.f, 0.f, 0.f};

    #pragma unroll
    for (int p = 0; p < NPAIR; ++p) {
        const unsigned long long* cp = sc + p * NCOEF;
        const ulonglong2* cv = reinterpret_cast<const ulonglong2*>(cp);

        unsigned long long y[4], q[4];
        q[0] = q[1] = q[2] = q[3] = 0ull;
        ulonglong2 wv;

        #pragma unroll
        for (int t = 0; t < 36; ++t) {
            if ((t & 1) == 0) wv = cv[t >> 1];
            unsigned long long w = (t & 1) ? wv.y : wv.x;
            const int i = TI[t], j = TJ[t];
            if (j == 0) {
                unsigned long long m = cp[36 + i];  // LDS.64, folded as FMA addend
                #pragma unroll
                for (int k = 0; k < 4; ++k) FMA2(y[k], w, X[k][0], m);
            } else {
                #pragma unroll
                for (int k = 0; k < 4; ++k) FMA2(y[k], w, X[k][j], y[k]);
            }
            if (j == i) {
                #pragma unroll
                for (int k = 0; k < 4; ++k) FMA2(q[k], y[k], y[k], q[k]);
            }
        }

        unsigned long long cc = cp[44];
        #pragma unroll
        for (int k = 0; k < 4; ++k) {
            unsigned long long l;
            FMA2(l, q[k], NEGH, cc);
            float va, vb;
            unpack2(l, va, vb);
            sa[k] += ex2f(va);
            sb[k] += ex2f(vb);
        }
    }

    const float LN2 = 0.69314718055994531f;
    #pragma unroll
    for (int k = 0; k < 4; ++k) {
        int pt = base + 32 * k;
        if (pt < n) out[pt] = fmaf(LN2, lg2f(sa[k] + sb[k]), cm);
    }
}

// ---------------------------------------------------------------------------
extern "C" void kernel_launch(void* const* d_in, const int* in_sizes, int n_in,
                              void* d_out, int out_size) {
    const float* x     = (const float*)d_in[0];
    const float* means = (const float*)d_in[1];
    const float* chol  = (const float*)d_in[2];
    const float* pi    = (const float*)d_in[3];
    float* out = (float*)d_out;

    int n = in_sizes[0] / DD;  // number of points

    gmm_precompute<<<1, 16>>>(means, chol, pi);

    int threads = 128;
    int pts_per_block = threads * 4;
    int blocks = (n + pts_per_block - 1) / pts_per_block;
    gmm_kernel<<<blocks, threads>>>(x, out, n);
}